// round 2
// baseline (speedup 1.0000x reference)
#include <cuda_runtime.h>
#include <math.h>

#define NB   8
#define SPA  1024      // 32*32 spatial positions
#define DM   128
#define NH   8
#define HD   1024      // NH*DM

// ---- scratch (device globals; no allocations anywhere) ----
__device__ float g_xn[NB*SPA*DM];     // layernormed x          4 MB
__device__ float g_Q [NB*SPA*HD];     // Q projection           32 MB
__device__ float g_K [NB*SPA*HD];     // K projection, spatial-swapped rows
__device__ float g_RS[NB*SPA*NH*32];  // row rel scores         8 MB
__device__ float g_CS[NB*SPA*NH*32];  // col rel scores         8 MB
__device__ float g_C [NB*SPA*HD];     // context                32 MB

#define INV_SQRT_D 0.08838834764831843f

// ============================================================ LayerNorm
__global__ void ln_kernel(const float* __restrict__ x,
                          const float* __restrict__ g,
                          const float* __restrict__ bb) {
    int row = blockIdx.x;          // b*1024 + s
    int t   = threadIdx.x;         // 128 threads
    float v = x[(long long)row*DM + t];
    float s = v, s2 = v*v;
    #pragma unroll
    for (int o = 16; o; o >>= 1) {
        s  += __shfl_xor_sync(0xffffffffu, s,  o);
        s2 += __shfl_xor_sync(0xffffffffu, s2, o);
    }
    __shared__ float rs[4], rs2[4];
    if ((t & 31) == 0) { rs[t>>5] = s; rs2[t>>5] = s2; }
    __syncthreads();
    float S  = rs[0]+rs[1]+rs[2]+rs[3];
    float S2 = rs2[0]+rs2[1]+rs2[2]+rs2[3];
    float mu  = S * (1.0f/128.0f);
    float var = S2 * (1.0f/128.0f) - mu*mu;
    float rstd = rsqrtf(var + 1e-5f);
    g_xn[(long long)row*DM + t] = (v - mu) * rstd * g[t] + bb[t];
}

// ============================================================ Q/K projection
// C[row, col] = sum_d xn[row,d] * W[col,d]; 64x64 tile, 256 thr, 4x4 per thread.
// which==1 -> K path: store with spatial swap  s' = (s&31)*32 + (s>>5)
__global__ void __launch_bounds__(256) proj_kernel(const float* __restrict__ W, int which) {
    __shared__ float At[32*68];   // [k][row]
    __shared__ float Wt[32*68];   // [k][col]
    float* out = which ? g_K : g_Q;
    int m0 = blockIdx.x * 64;     // 128 tiles over 8192 rows
    int n0 = blockIdx.y * 64;     // 16 tiles over 1024 cols
    int tid = threadIdx.x;
    int og = tid & 15, sg = tid >> 4;
    float acc[16];
    #pragma unroll
    for (int i = 0; i < 16; i++) acc[i] = 0.f;

    for (int kc = 0; kc < 128; kc += 32) {
        for (int i = tid; i < 2048; i += 256) {
            int k = i & 31, r = i >> 5;
            At[k*68 + r] = g_xn[(long long)(m0 + r)*128 + kc + k];
            Wt[k*68 + r] = W[(long long)(n0 + r)*128 + kc + k];
        }
        __syncthreads();
        #pragma unroll 8
        for (int k = 0; k < 32; k++) {
            float4 a = *(const float4*)&At[k*68 + sg*4];
            float4 w = *(const float4*)&Wt[k*68 + og*4];
            acc[ 0] += a.x*w.x; acc[ 1] += a.x*w.y; acc[ 2] += a.x*w.z; acc[ 3] += a.x*w.w;
            acc[ 4] += a.y*w.x; acc[ 5] += a.y*w.y; acc[ 6] += a.y*w.z; acc[ 7] += a.y*w.w;
            acc[ 8] += a.z*w.x; acc[ 9] += a.z*w.y; acc[10] += a.z*w.z; acc[11] += a.z*w.w;
            acc[12] += a.w*w.x; acc[13] += a.w*w.y; acc[14] += a.w*w.z; acc[15] += a.w*w.w;
        }
        __syncthreads();
    }
    #pragma unroll
    for (int i = 0; i < 4; i++) {
        int row = m0 + sg*4 + i;
        int orow = row;
        if (which) {
            int b = row >> 10, s = row & 1023;
            orow = (b << 10) | ((s & 31)*32 + (s >> 5));
        }
        float4 st = make_float4(acc[i*4+0], acc[i*4+1], acc[i*4+2], acc[i*4+3]);
        *(float4*)&out[(long long)orow*1024 + n0 + og*4] = st;
    }
}

// ============================================================ relative-embedding scores
// RS[b,s,h,v] = sum_{d<64}  Q[b,s,h*128+d]    * row_emb[v - iq + 31][d]   (iq = s>>5)
// CS[b,s,h,u] = sum_{d<64}  Q[b,s,h*128+64+d] * col_emb[u - jq + 31][d]   (jq = s&31)
__global__ void __launch_bounds__(256) rel_kernel(const float* __restrict__ re_emb,
                                                  const float* __restrict__ ce_emb) {
    int bs = blockIdx.x;                 // 0..8191
    int s  = bs & 1023;
    int iq = s >> 5, jq = s & 31;
    __shared__ float qr[1024];
    __shared__ float re[32*65];
    __shared__ float ce[32*65];
    int tid = threadIdx.x;
    for (int i = tid; i < 1024; i += 256) qr[i] = g_Q[(long long)bs*1024 + i];
    for (int i = tid; i < 2048; i += 256) {
        int v = i >> 6, d = i & 63;
        re[v*65 + d] = re_emb[(v - iq + 31)*64 + d];
        ce[v*65 + d] = ce_emb[(v - jq + 31)*64 + d];
    }
    __syncthreads();
    int h = tid >> 5, v = tid & 31;
    float a = 0.f, c = 0.f;
    #pragma unroll
    for (int d = 0; d < 64; d++) {
        a += qr[h*128 + d]      * re[v*65 + d];
        c += qr[h*128 + 64 + d] * ce[v*65 + d];
    }
    g_RS[((long long)bs*8 + h)*32 + v] = a;
    g_CS[((long long)bs*8 + h)*32 + v] = c;
}

// ============================================================ fused attention
// block = (iq, h, b); 32 queries (jq = 0..31), full 1024-key score row in smem.
// Phase 1: S = Q*K_swap^T   Phase 2: bias+scale+softmax (+probs out)
// Phase 3: context = P @ xn
#define ATTN_SMEM_FLOATS (32*1024 + 128*36 + 128*132 + 1024 + 1024)
__global__ void __launch_bounds__(256, 1) attn_kernel(float* __restrict__ probs) {
    extern __shared__ float sm[];
    float* S   = sm;                 // 32 x 1024
    float* Qt  = sm + 32*1024;       // [d][q]   pitch 36
    float* Kt  = Qt + 128*36;        // [d][key] pitch 132  (reused as Xs[64][132])
    float* RSs = Kt + 128*132;       // 32 x 32
    float* CSs = RSs + 1024;         // 32 x 32

    int iq = blockIdx.x, h = blockIdx.y, b = blockIdx.z;
    int tid = threadIdx.x;
    int qg = tid >> 5, kg = tid & 31;

    long long qbase = ((long long)(b*1024 + iq*32))*1024 + h*128;
    for (int i = tid; i < 4096; i += 256) {
        int j = i >> 7, d = i & 127;
        Qt[d*36 + j] = g_Q[qbase + (long long)j*1024 + d];
    }
    for (int i = tid; i < 1024; i += 256) {
        int j = i >> 5, v = i & 31;
        long long rb = ((long long)(b*1024 + iq*32 + j)*8 + h)*32 + v;
        RSs[i] = g_RS[rb];
        CSs[i] = g_CS[rb];
    }
    __syncthreads();

    // -------- Phase 1: content scores --------
    long long kbaseb = ((long long)b*1024)*1024 + h*128;
    for (int kt = 0; kt < 8; kt++) {
        for (int i = tid; i < 16384; i += 256) {
            int d = i & 127, r = i >> 7;
            Kt[d*132 + r] = g_K[kbaseb + (long long)(kt*128 + r)*1024 + d];
        }
        __syncthreads();
        float acc[16];
        #pragma unroll
        for (int i = 0; i < 16; i++) acc[i] = 0.f;
        #pragma unroll 4
        for (int d = 0; d < 128; d++) {
            float4 qf = *(const float4*)&Qt[d*36 + qg*4];
            float4 kf = *(const float4*)&Kt[d*132 + kg*4];
            acc[ 0] += qf.x*kf.x; acc[ 1] += qf.x*kf.y; acc[ 2] += qf.x*kf.z; acc[ 3] += qf.x*kf.w;
            acc[ 4] += qf.y*kf.x; acc[ 5] += qf.y*kf.y; acc[ 6] += qf.y*kf.z; acc[ 7] += qf.y*kf.w;
            acc[ 8] += qf.z*kf.x; acc[ 9] += qf.z*kf.y; acc[10] += qf.z*kf.z; acc[11] += qf.z*kf.w;
            acc[12] += qf.w*kf.x; acc[13] += qf.w*kf.y; acc[14] += qf.w*kf.z; acc[15] += qf.w*kf.w;
        }
        #pragma unroll
        for (int i = 0; i < 4; i++) {
            *(float4*)&S[(qg*4+i)*1024 + kt*128 + kg*4] =
                make_float4(acc[i*4+0], acc[i*4+1], acc[i*4+2], acc[i*4+3]);
        }
        __syncthreads();
    }

    // -------- Phase 2: bias + scale + softmax (+ probs output) --------
    {
        int lane = tid & 31, wid = tid >> 5;
        for (int rr = 0; rr < 4; rr++) {
            int q = wid*4 + rr;                 // q == jq (local query)
            float* Srow = S + q*1024;
            float mx = -1e30f;
            for (int j = lane; j < 1024; j += 32) {
                float val = (Srow[j] + RSs[q*32 + (j & 31)] + CSs[q*32 + (j >> 5)]) * INV_SQRT_D;
                Srow[j] = val;
                mx = fmaxf(mx, val);
            }
            #pragma unroll
            for (int o = 16; o; o >>= 1) mx = fmaxf(mx, __shfl_xor_sync(0xffffffffu, mx, o));
            float sum = 0.f;
            for (int j = lane; j < 1024; j += 32) {
                float e = __expf(Srow[j] - mx);
                Srow[j] = e;
                sum += e;
            }
            #pragma unroll
            for (int o = 16; o; o >>= 1) sum += __shfl_xor_sync(0xffffffffu, sum, o);
            float is = 1.0f / sum;
            if (probs) {
                long long pb = ((((long long)b*32 + q)*32 + iq)*8 + h)*1024;
                for (int j = lane; j < 1024; j += 32) {
                    float p = Srow[j] * is;
                    Srow[j] = p;
                    probs[pb + j] = p;
                }
            } else {
                for (int j = lane; j < 1024; j += 32) Srow[j] *= is;
            }
        }
    }
    __syncthreads();

    // -------- Phase 3: context = P @ xn --------
    float* Xs = Kt;                   // reuse K-tile smem: 64 x 132
    int dg = kg;
    float c4[16];
    #pragma unroll
    for (int i = 0; i < 16; i++) c4[i] = 0.f;
    for (int tt = 0; tt < 16; tt++) {
        for (int i = tid; i < 2048; i += 256) {    // 64 rows x 32 float4
            int t = i >> 5, dq = i & 31;
            *(float4*)&Xs[t*132 + dq*4] =
                *(const float4*)&g_xn[(long long)(b*1024 + tt*64 + t)*128 + dq*4];
        }
        __syncthreads();
        #pragma unroll 4
        for (int t = 0; t < 64; t++) {
            float4 xf = *(const float4*)&Xs[t*132 + dg*4];
            int col = tt*64 + t;
            float p0 = S[(qg*4+0)*1024 + col];
            float p1 = S[(qg*4+1)*1024 + col];
            float p2 = S[(qg*4+2)*1024 + col];
            float p3 = S[(qg*4+3)*1024 + col];
            c4[ 0] += p0*xf.x; c4[ 1] += p0*xf.y; c4[ 2] += p0*xf.z; c4[ 3] += p0*xf.w;
            c4[ 4] += p1*xf.x; c4[ 5] += p1*xf.y; c4[ 6] += p1*xf.z; c4[ 7] += p1*xf.w;
            c4[ 8] += p2*xf.x; c4[ 9] += p2*xf.y; c4[10] += p2*xf.z; c4[11] += p2*xf.w;
            c4[12] += p3*xf.x; c4[13] += p3*xf.y; c4[14] += p3*xf.z; c4[15] += p3*xf.w;
        }
        __syncthreads();
    }
    #pragma unroll
    for (int i = 0; i < 4; i++) {
        int sp = (qg*4+i)*32 + iq;     // output spatial row = jq*32 + iq
        *(float4*)&g_C[(long long)(b*1024 + sp)*1024 + h*128 + dg*4] =
            make_float4(c4[i*4+0], c4[i*4+1], c4[i*4+2], c4[i*4+3]);
    }
}

// ============================================================ output projection + residual
// out[row, o] = sum_c C[row,c]*Wv[o,c] + bv[o] + xn[row,o]
__global__ void __launch_bounds__(512) out_kernel(const float* __restrict__ Wv,
                                                  const float* __restrict__ bv,
                                                  float* __restrict__ out) {
    __shared__ float At[32*68];    // [k][row], 64 rows
    __shared__ float Wt[32*132];   // [k][o],  128 o
    int m0 = blockIdx.x * 64;
    int tid = threadIdx.x;
    int og = tid & 31, sg = tid >> 5;   // 32 o-groups x 16 row-groups
    float acc[16];
    #pragma unroll
    for (int i = 0; i < 16; i++) acc[i] = 0.f;

    for (int kc = 0; kc < 1024; kc += 32) {
        for (int i = tid; i < 2048; i += 512) {
            int k = i & 31, r = i >> 5;
            At[k*68 + r] = g_C[(long long)(m0 + r)*1024 + kc + k];
        }
        for (int i = tid; i < 4096; i += 512) {
            int k = i & 31, o = i >> 5;
            Wt[k*132 + o] = Wv[(long long)o*1024 + kc + k];
        }
        __syncthreads();
        #pragma unroll 8
        for (int k = 0; k < 32; k++) {
            float4 a = *(const float4*)&At[k*68 + sg*4];
            float4 w = *(const float4*)&Wt[k*132 + og*4];
            acc[ 0] += a.x*w.x; acc[ 1] += a.x*w.y; acc[ 2] += a.x*w.z; acc[ 3] += a.x*w.w;
            acc[ 4] += a.y*w.x; acc[ 5] += a.y*w.y; acc[ 6] += a.y*w.z; acc[ 7] += a.y*w.w;
            acc[ 8] += a.z*w.x; acc[ 9] += a.z*w.y; acc[10] += a.z*w.z; acc[11] += a.z*w.w;
            acc[12] += a.w*w.x; acc[13] += a.w*w.y; acc[14] += a.w*w.z; acc[15] += a.w*w.w;
        }
        __syncthreads();
    }
    if (out) {
        float4 b4 = *(const float4*)&bv[og*4];
        #pragma unroll
        for (int i = 0; i < 4; i++) {
            int row = m0 + sg*4 + i;
            float4 x4 = *(const float4*)&g_xn[(long long)row*128 + og*4];
            float4 r4;
            r4.x = acc[i*4+0] + b4.x + x4.x;
            r4.y = acc[i*4+1] + b4.y + x4.y;
            r4.z = acc[i*4+2] + b4.z + x4.z;
            r4.w = acc[i*4+3] + b4.w + x4.w;
            *(float4*)&out[(long long)row*128 + og*4] = r4;
        }
    }
}

// ============================================================ launch
extern "C" void kernel_launch(void* const* d_in, const int* in_sizes, int n_in,
                              void* d_out, int out_size) {
    const float* x   = (const float*)d_in[0];
    const float* rem = (const float*)d_in[1];
    const float* cem = (const float*)d_in[2];
    const float* Wq  = (const float*)d_in[3];
    const float* Wk  = (const float*)d_in[4];
    const float* Wv  = (const float*)d_in[5];
    const float* bv  = (const float*)d_in[6];
    const float* lg  = (const float*)d_in[7];
    const float* lb  = (const float*)d_in[8];

    const long long ON = 1048576LL;        // output elems
    const long long PN = 67108864LL;       // probs elems
    float* outp  = (float*)d_out;
    float* probs = nullptr;
    if ((long long)out_size >= ON + PN) {
        probs = (float*)d_out + ON;
    } else if ((long long)out_size == PN) {
        probs = (float*)d_out;
        outp  = nullptr;
    }

    static int smem_ok = -1;
    if (smem_ok < 0) {
        cudaError_t e = cudaFuncSetAttribute(
            attn_kernel, cudaFuncAttributeMaxDynamicSharedMemorySize,
            ATTN_SMEM_FLOATS * (int)sizeof(float));
        smem_ok = (e == cudaSuccess) ? 1 : 0;
        if (!smem_ok) cudaGetLastError();   // clear sticky error; launch will fail loudly instead
    }

    ln_kernel<<<8192, 128>>>(x, lg, lb);
    proj_kernel<<<dim3(128, 16), 256>>>(Wq, 0);
    proj_kernel<<<dim3(128, 16), 256>>>(Wk, 1);
    rel_kernel<<<8192, 256>>>(rem, cem);
    attn_kernel<<<dim3(32, NH, NB), 256, ATTN_SMEM_FLOATS * sizeof(float)>>>(probs);
    out_kernel<<<128, 512>>>(Wv, bv, outp);
}

// round 4
// speedup vs baseline: 1.3262x; 1.3262x over previous
#include <cuda_runtime.h>
#include <math.h>

#define NB   8
#define SPA  1024      // 32*32 spatial positions
#define DM   128
#define NH   8
#define HD   1024      // NH*DM

// ---- scratch (device globals; no allocations anywhere) ----
__device__ float g_xn[NB*SPA*DM];     // layernormed x          4 MB
__device__ float g_Q [NB*SPA*HD];     // Q projection           32 MB
__device__ float g_K [NB*SPA*HD];     // K projection, spatial-swapped rows
__device__ float g_RS[NB*SPA*NH*32];  // row rel scores         8 MB
__device__ float g_CS[NB*SPA*NH*32];  // col rel scores         8 MB
__device__ float g_C [NB*SPA*HD];     // context                32 MB

#define INV_SQRT_D 0.08838834764831843f

// ============================================================ LayerNorm
__global__ void ln_kernel(const float* __restrict__ x,
                          const float* __restrict__ g,
                          const float* __restrict__ bb) {
    int row = blockIdx.x;          // b*1024 + s
    int t   = threadIdx.x;         // 128 threads
    float v = x[(long long)row*DM + t];
    float s = v, s2 = v*v;
    #pragma unroll
    for (int o = 16; o; o >>= 1) {
        s  += __shfl_xor_sync(0xffffffffu, s,  o);
        s2 += __shfl_xor_sync(0xffffffffu, s2, o);
    }
    __shared__ float rs[4], rs2[4];
    if ((t & 31) == 0) { rs[t>>5] = s; rs2[t>>5] = s2; }
    __syncthreads();
    float S  = rs[0]+rs[1]+rs[2]+rs[3];
    float S2 = rs2[0]+rs2[1]+rs2[2]+rs2[3];
    float mu  = S * (1.0f/128.0f);
    float var = S2 * (1.0f/128.0f) - mu*mu;
    float rstd = rsqrtf(var + 1e-5f);
    g_xn[(long long)row*DM + t] = (v - mu) * rstd * g[t] + bb[t];
}

// ============================================================ Q/K projection
// C[row, col] = sum_d xn[row,d] * W[col,d]; 64x64 tile, 256 thr, 4x4 per thread.
// which==1 -> K path: store with spatial swap  s' = (s&31)*32 + (s>>5)
__global__ void __launch_bounds__(256) proj_kernel(const float* __restrict__ W, int which) {
    __shared__ float At[32*68];   // [k][row]
    __shared__ float Wt[32*68];   // [k][col]
    float* out = which ? g_K : g_Q;
    int m0 = blockIdx.x * 64;     // 128 tiles over 8192 rows
    int n0 = blockIdx.y * 64;     // 16 tiles over 1024 cols
    int tid = threadIdx.x;
    int og = tid & 15, sg = tid >> 4;
    float acc[16];
    #pragma unroll
    for (int i = 0; i < 16; i++) acc[i] = 0.f;

    for (int kc = 0; kc < 128; kc += 32) {
        for (int i = tid; i < 2048; i += 256) {
            int k = i & 31, r = i >> 5;
            At[k*68 + r] = g_xn[(long long)(m0 + r)*128 + kc + k];
            Wt[k*68 + r] = W[(long long)(n0 + r)*128 + kc + k];
        }
        __syncthreads();
        #pragma unroll 8
        for (int k = 0; k < 32; k++) {
            float4 a = *(const float4*)&At[k*68 + sg*4];
            float4 w = *(const float4*)&Wt[k*68 + og*4];
            acc[ 0] += a.x*w.x; acc[ 1] += a.x*w.y; acc[ 2] += a.x*w.z; acc[ 3] += a.x*w.w;
            acc[ 4] += a.y*w.x; acc[ 5] += a.y*w.y; acc[ 6] += a.y*w.z; acc[ 7] += a.y*w.w;
            acc[ 8] += a.z*w.x; acc[ 9] += a.z*w.y; acc[10] += a.z*w.z; acc[11] += a.z*w.w;
            acc[12] += a.w*w.x; acc[13] += a.w*w.y; acc[14] += a.w*w.z; acc[15] += a.w*w.w;
        }
        __syncthreads();
    }
    #pragma unroll
    for (int i = 0; i < 4; i++) {
        int row = m0 + sg*4 + i;
        int orow = row;
        if (which) {
            int b = row >> 10, s = row & 1023;
            orow = (b << 10) | ((s & 31)*32 + (s >> 5));
        }
        float4 st = make_float4(acc[i*4+0], acc[i*4+1], acc[i*4+2], acc[i*4+3]);
        *(float4*)&out[(long long)orow*1024 + n0 + og*4] = st;
    }
}

// ============================================================ relative-embedding scores
// RS[b,s,h,v] = sum_{d<64}  Q[b,s,h*128+d]    * row_emb[v - iq + 31][d]   (iq = s>>5)
// CS[b,s,h,u] = sum_{d<64}  Q[b,s,h*128+64+d] * col_emb[u - jq + 31][d]   (jq = s&31)
__global__ void __launch_bounds__(256) rel_kernel(const float* __restrict__ re_emb,
                                                  const float* __restrict__ ce_emb) {
    int bs = blockIdx.x;                 // 0..8191
    int s  = bs & 1023;
    int iq = s >> 5, jq = s & 31;
    __shared__ float qr[1024];
    __shared__ float re[32*68];
    __shared__ float ce[32*68];
    int tid = threadIdx.x;
    for (int i = tid; i < 256; i += 256)
        *(float4*)&qr[i*4] = *(const float4*)&g_Q[(long long)bs*1024 + i*4];
    for (int i = tid; i < 512; i += 256) {
        int v = i >> 4, d4 = i & 15;
        *(float4*)&re[v*68 + d4*4] = *(const float4*)&re_emb[(v - iq + 31)*64 + d4*4];
        *(float4*)&ce[v*68 + d4*4] = *(const float4*)&ce_emb[(v - jq + 31)*64 + d4*4];
    }
    __syncthreads();
    int h = tid >> 5, v = tid & 31;
    float a = 0.f, c = 0.f;
    #pragma unroll
    for (int dd = 0; dd < 16; dd++) {
        float4 qa = *(const float4*)&qr[h*128 + dd*4];
        float4 qb = *(const float4*)&qr[h*128 + 64 + dd*4];
        float4 rr = *(const float4*)&re[v*68 + dd*4];
        float4 cc = *(const float4*)&ce[v*68 + dd*4];
        a += qa.x*rr.x + qa.y*rr.y + qa.z*rr.z + qa.w*rr.w;
        c += qb.x*cc.x + qb.y*cc.y + qb.z*cc.z + qb.w*cc.w;
    }
    g_RS[((long long)bs*8 + h)*32 + v] = a;
    g_CS[((long long)bs*8 + h)*32 + v] = c;
}

// ============================================================ fused attention
// block = (iq, h, b); 32 queries (jq = 0..31), full 1024-key score row in smem.
// 512 threads: phase1 splits reduction d across thread halves; phase3 splits k.
#define ATTN_SMEM_FLOATS (32*1024 + 128*36 + 128*132 + 1024 + 1024)
__global__ void __launch_bounds__(512, 1) attn_kernel(float* __restrict__ probs) {
    extern __shared__ float sm[];
    float* S   = sm;                 // 32 x 1024 (scores -> probs)
    float* Qt  = sm + 32*1024;       // [d][q] pitch 36 ; later: phase-3 partial scratch
    float* Kt  = Qt + 128*36;        // [d][key] pitch 132 (reused as Xs[128][132])
    float* RSs = Kt + 128*132;       // 32 x 32
    float* CSs = RSs + 1024;         // 32 x 32

    int iq = blockIdx.x, h = blockIdx.y, b = blockIdx.z;
    int tid  = threadIdx.x;
    int half = tid >> 8;             // 0 / 1
    int pos  = tid & 255;
    int qg   = pos >> 5;             // 0..7
    int kg   = pos & 31;             // 0..31

    long long qbase = ((long long)(b*1024 + iq*32))*1024 + h*128;
    for (int i = tid; i < 4096; i += 512) {
        int j = i >> 7, d = i & 127;
        Qt[d*36 + j] = g_Q[qbase + (long long)j*1024 + d];
    }
    for (int i = tid; i < 1024; i += 512) {
        int j = i >> 5, v = i & 31;
        long long rb = ((long long)(b*1024 + iq*32 + j)*8 + h)*32 + v;
        RSs[i] = g_RS[rb];
        CSs[i] = g_CS[rb];
    }
    __syncthreads();

    // -------- Phase 1: content scores (d-split across halves) --------
    long long kbaseb = ((long long)b*1024)*1024 + h*128;
    int d0 = half * 64;
    for (int kt = 0; kt < 8; kt++) {
        for (int i = tid; i < 16384; i += 512) {
            int d = i & 127, r = i >> 7;
            Kt[d*132 + r] = g_K[kbaseb + (long long)(kt*128 + r)*1024 + d];
        }
        __syncthreads();
        float acc[16];
        #pragma unroll
        for (int i = 0; i < 16; i++) acc[i] = 0.f;
        #pragma unroll 4
        for (int dd = 0; dd < 64; dd++) {
            int d = d0 + dd;
            float4 qf = *(const float4*)&Qt[d*36 + qg*4];
            float4 kf = *(const float4*)&Kt[d*132 + kg*4];
            acc[ 0] += qf.x*kf.x; acc[ 1] += qf.x*kf.y; acc[ 2] += qf.x*kf.z; acc[ 3] += qf.x*kf.w;
            acc[ 4] += qf.y*kf.x; acc[ 5] += qf.y*kf.y; acc[ 6] += qf.y*kf.z; acc[ 7] += qf.y*kf.w;
            acc[ 8] += qf.z*kf.x; acc[ 9] += qf.z*kf.y; acc[10] += qf.z*kf.z; acc[11] += qf.z*kf.w;
            acc[12] += qf.w*kf.x; acc[13] += qf.w*kf.y; acc[14] += qf.w*kf.z; acc[15] += qf.w*kf.w;
        }
        __syncthreads();
        if (half == 0) {
            #pragma unroll
            for (int i = 0; i < 4; i++)
                *(float4*)&S[(qg*4+i)*1024 + kt*128 + kg*4] =
                    make_float4(acc[i*4+0], acc[i*4+1], acc[i*4+2], acc[i*4+3]);
        }
        __syncthreads();
        if (half == 1) {
            #pragma unroll
            for (int i = 0; i < 4; i++) {
                float4* p = (float4*)&S[(qg*4+i)*1024 + kt*128 + kg*4];
                float4 v = *p;
                v.x += acc[i*4+0]; v.y += acc[i*4+1]; v.z += acc[i*4+2]; v.w += acc[i*4+3];
                *p = v;
            }
        }
        __syncthreads();
    }

    // -------- Phase 2: bias + scale + softmax (+ probs output) --------
    {
        int lane = tid & 31, wid = tid >> 5;     // 16 warps, 2 rows each
        for (int rr = 0; rr < 2; rr++) {
            int q = wid*2 + rr;                  // q == jq (local query)
            float* Srow = S + q*1024;
            float mx = -1e30f;
            for (int j = lane; j < 1024; j += 32) {
                float val = (Srow[j] + RSs[q*32 + (j & 31)] + CSs[q*32 + (j >> 5)]) * INV_SQRT_D;
                Srow[j] = val;
                mx = fmaxf(mx, val);
            }
            #pragma unroll
            for (int o = 16; o; o >>= 1) mx = fmaxf(mx, __shfl_xor_sync(0xffffffffu, mx, o));
            float sum = 0.f;
            for (int j = lane; j < 1024; j += 32) {
                float e = __expf(Srow[j] - mx);
                Srow[j] = e;
                sum += e;
            }
            #pragma unroll
            for (int o = 16; o; o >>= 1) sum += __shfl_xor_sync(0xffffffffu, sum, o);
            float is = 1.0f / sum;
            if (probs) {
                long long pb = ((((long long)b*32 + q)*32 + iq)*8 + h)*1024;
                for (int j = lane; j < 1024; j += 32) {
                    float p = Srow[j] * is;
                    Srow[j] = p;
                    probs[pb + j] = p;
                }
            } else {
                for (int j = lane; j < 1024; j += 32) Srow[j] *= is;
            }
        }
    }
    __syncthreads();

    // -------- Phase 3: context = P @ xn (k-split across halves) --------
    float* Xs = Kt;                 // 128 rows x pitch 132
    float* Pscr = Qt;               // scratch for half1 partials: 32*128 floats
    int dg = kg;                    // dim group 0..31 (4 dims each)
    int kbase = half * 512;
    float c4[16];
    #pragma unroll
    for (int i = 0; i < 16; i++) c4[i] = 0.f;
    for (int tt = 0; tt < 8; tt++) {
        // rows 0..63 of Xs: keys tt*64.. ; rows 64..127: keys 512 + tt*64..
        for (int i = tid; i < 4096; i += 512) {     // 128 rows x 32 float4
            int row = i >> 5, dq = i & 31;
            int key = (row < 64) ? (tt*64 + row) : (512 + tt*64 + (row - 64));
            *(float4*)&Xs[row*132 + dq*4] =
                *(const float4*)&g_xn[(long long)(b*1024 + key)*128 + dq*4];
        }
        __syncthreads();
        int xrow0 = half * 64;
        int col0  = kbase + tt*64;
        #pragma unroll 4
        for (int t = 0; t < 64; t++) {
            float4 xf = *(const float4*)&Xs[(xrow0 + t)*132 + dg*4];
            int col = col0 + t;
            float p0 = S[(qg*4+0)*1024 + col];
            float p1 = S[(qg*4+1)*1024 + col];
            float p2 = S[(qg*4+2)*1024 + col];
            float p3 = S[(qg*4+3)*1024 + col];
            c4[ 0] += p0*xf.x; c4[ 1] += p0*xf.y; c4[ 2] += p0*xf.z; c4[ 3] += p0*xf.w;
            c4[ 4] += p1*xf.x; c4[ 5] += p1*xf.y; c4[ 6] += p1*xf.z; c4[ 7] += p1*xf.w;
            c4[ 8] += p2*xf.x; c4[ 9] += p2*xf.y; c4[10] += p2*xf.z; c4[11] += p2*xf.w;
            c4[12] += p3*xf.x; c4[13] += p3*xf.y; c4[14] += p3*xf.z; c4[15] += p3*xf.w;
        }
        __syncthreads();
    }
    // merge halves: half1 -> scratch, half0 adds + stores
    if (half == 1) {
        #pragma unroll
        for (int i = 0; i < 4; i++)
            *(float4*)&Pscr[(qg*4+i)*128 + dg*4] =
                make_float4(c4[i*4+0], c4[i*4+1], c4[i*4+2], c4[i*4+3]);
    }
    __syncthreads();
    if (half == 0) {
        #pragma unroll
        for (int i = 0; i < 4; i++) {
            float4 o = *(const float4*)&Pscr[(qg*4+i)*128 + dg*4];
            o.x += c4[i*4+0]; o.y += c4[i*4+1]; o.z += c4[i*4+2]; o.w += c4[i*4+3];
            int sp = (qg*4+i)*32 + iq;     // output spatial row = jq*32 + iq
            *(float4*)&g_C[(long long)(b*1024 + sp)*1024 + h*128 + dg*4] = o;
        }
    }
}

// ============================================================ output projection + residual
// out[row, o] = sum_c C[row,c]*Wv[o,c] + bv[o] + xn[row,o]
__global__ void __launch_bounds__(512) out_kernel(const float* __restrict__ Wv,
                                                  const float* __restrict__ bv,
                                                  float* __restrict__ out) {
    __shared__ float At[32*68];    // [k][row], 64 rows
    __shared__ float Wt[32*132];   // [k][o],  128 o
    int m0 = blockIdx.x * 64;
    int tid = threadIdx.x;
    int og = tid & 31, sg = tid >> 5;   // 32 o-groups x 16 row-groups
    float acc[16];
    #pragma unroll
    for (int i = 0; i < 16; i++) acc[i] = 0.f;

    for (int kc = 0; kc < 1024; kc += 32) {
        for (int i = tid; i < 2048; i += 512) {
            int k = i & 31, r = i >> 5;
            At[k*68 + r] = g_C[(long long)(m0 + r)*1024 + kc + k];
        }
        for (int i = tid; i < 4096; i += 512) {
            int k = i & 31, o = i >> 5;
            Wt[k*132 + o] = Wv[(long long)o*1024 + kc + k];
        }
        __syncthreads();
        #pragma unroll 8
        for (int k = 0; k < 32; k++) {
            float4 a = *(const float4*)&At[k*68 + sg*4];
            float4 w = *(const float4*)&Wt[k*132 + og*4];
            acc[ 0] += a.x*w.x; acc[ 1] += a.x*w.y; acc[ 2] += a.x*w.z; acc[ 3] += a.x*w.w;
            acc[ 4] += a.y*w.x; acc[ 5] += a.y*w.y; acc[ 6] += a.y*w.z; acc[ 7] += a.y*w.w;
            acc[ 8] += a.z*w.x; acc[ 9] += a.z*w.y; acc[10] += a.z*w.z; acc[11] += a.z*w.w;
            acc[12] += a.w*w.x; acc[13] += a.w*w.y; acc[14] += a.w*w.z; acc[15] += a.w*w.w;
        }
        __syncthreads();
    }
    if (out) {
        float4 b4 = *(const float4*)&bv[og*4];
        #pragma unroll
        for (int i = 0; i < 4; i++) {
            int row = m0 + sg*4 + i;
            float4 x4 = *(const float4*)&g_xn[(long long)row*128 + og*4];
            float4 r4;
            r4.x = acc[i*4+0] + b4.x + x4.x;
            r4.y = acc[i*4+1] + b4.y + x4.y;
            r4.z = acc[i*4+2] + b4.z + x4.z;
            r4.w = acc[i*4+3] + b4.w + x4.w;
            *(float4*)&out[(long long)row*128 + og*4] = r4;
        }
    }
}

// ============================================================ launch
extern "C" void kernel_launch(void* const* d_in, const int* in_sizes, int n_in,
                              void* d_out, int out_size) {
    const float* x   = (const float*)d_in[0];
    const float* rem = (const float*)d_in[1];
    const float* cem = (const float*)d_in[2];
    const float* Wq  = (const float*)d_in[3];
    const float* Wk  = (const float*)d_in[4];
    const float* Wv  = (const float*)d_in[5];
    const float* bv  = (const float*)d_in[6];
    const float* lg  = (const float*)d_in[7];
    const float* lb  = (const float*)d_in[8];

    const long long ON = 1048576LL;        // output elems
    const long long PN = 67108864LL;       // probs elems
    float* outp  = (float*)d_out;
    float* probs = nullptr;
    if ((long long)out_size >= ON + PN) {
        probs = (float*)d_out + ON;
    } else if ((long long)out_size == PN) {
        probs = (float*)d_out;
        outp  = nullptr;
    }

    static int smem_ok = -1;
    if (smem_ok < 0) {
        cudaError_t e = cudaFuncSetAttribute(
            attn_kernel, cudaFuncAttributeMaxDynamicSharedMemorySize,
            ATTN_SMEM_FLOATS * (int)sizeof(float));
        smem_ok = (e == cudaSuccess) ? 1 : 0;
        if (!smem_ok) cudaGetLastError();
    }

    ln_kernel<<<8192, 128>>>(x, lg, lb);
    proj_kernel<<<dim3(128, 16), 256>>>(Wq, 0);
    proj_kernel<<<dim3(128, 16), 256>>>(Wk, 1);
    rel_kernel<<<8192, 256>>>(rem, cem);
    attn_kernel<<<dim3(32, NH, NB), 512, ATTN_SMEM_FLOATS * sizeof(float)>>>(probs);
    out_kernel<<<128, 512>>>(Wv, bv, outp);
}

// round 7
// speedup vs baseline: 2.0584x; 1.5520x over previous
#include <cuda_runtime.h>
#include <cuda_bf16.h>
#include <math.h>
#include <stdint.h>

#define NB   8
#define SPA  1024
#define DM   128
#define NH   8
#define HD   1024

// ---- scratch (device globals; no allocations anywhere) ----
__device__ float g_xn[NB*SPA*DM];                 // layernormed x (fp32)
__device__ float g_Q [NB*SPA*HD];                 // Q fp32 (for rel_kernel)
__device__ float g_RS[NB*SPA*NH*32];
__device__ float g_CS[NB*SPA*NH*32];
__device__ float g_C [NB*SPA*HD];                 // context
// bf16 hi/lo operand banks, per-head layout [b][h][s][d]
__device__ __nv_bfloat16 g_qhi[NB*NH*SPA*DM];
__device__ __nv_bfloat16 g_qlo[NB*NH*SPA*DM];
__device__ __nv_bfloat16 g_khi[NB*NH*SPA*DM];    // key index spatially swapped
__device__ __nv_bfloat16 g_klo[NB*NH*SPA*DM];
// xn transposed [b][d][key]
__device__ __nv_bfloat16 g_xthi[NB*DM*SPA];
__device__ __nv_bfloat16 g_xtlo[NB*DM*SPA];

#define INV_SQRT_D 0.08838834764831843f

// ============================================================ mma helpers
__device__ __forceinline__ uint32_t smem_u32(const void* p) {
    uint32_t a;
    asm("{ .reg .u64 t; cvta.to.shared.u64 t, %1; cvt.u32.u64 %0, t; }" : "=r"(a) : "l"(p));
    return a;
}
__device__ __forceinline__ void ldm_x4(uint32_t* r, uint32_t addr) {
    asm volatile("ldmatrix.sync.aligned.m8n8.x4.shared.b16 {%0,%1,%2,%3}, [%4];"
        : "=r"(r[0]), "=r"(r[1]), "=r"(r[2]), "=r"(r[3]) : "r"(addr));
}
__device__ __forceinline__ void ldm_x2(uint32_t* r, uint32_t addr) {
    asm volatile("ldmatrix.sync.aligned.m8n8.x2.shared.b16 {%0,%1}, [%2];"
        : "=r"(r[0]), "=r"(r[1]) : "r"(addr));
}
__device__ __forceinline__ void mma16816(float* c, const uint32_t* a, const uint32_t* b) {
    asm volatile("mma.sync.aligned.m16n8k16.row.col.f32.bf16.bf16.f32 "
        "{%0,%1,%2,%3}, {%4,%5,%6,%7}, {%8,%9}, {%0,%1,%2,%3};"
        : "+f"(c[0]), "+f"(c[1]), "+f"(c[2]), "+f"(c[3])
        : "r"(a[0]), "r"(a[1]), "r"(a[2]), "r"(a[3]), "r"(b[0]), "r"(b[1]));
}
__device__ __forceinline__ void cvt_hilo(float a, __nv_bfloat16& hi, __nv_bfloat16& lo) {
    hi = __float2bfloat16(a);
    lo = __float2bfloat16(a - __bfloat162float(hi));
}
__device__ __forceinline__ uint32_t pack2(__nv_bfloat16 a, __nv_bfloat16 b) {
    return (uint32_t)__bfloat16_as_ushort(a) | ((uint32_t)__bfloat16_as_ushort(b) << 16);
}

// ============================================================ LayerNorm
__global__ void ln_kernel(const float* __restrict__ x,
                          const float* __restrict__ g,
                          const float* __restrict__ bb) {
    int row = blockIdx.x;
    int t   = threadIdx.x;
    float v = x[(long long)row*DM + t];
    float s = v, s2 = v*v;
    #pragma unroll
    for (int o = 16; o; o >>= 1) {
        s  += __shfl_xor_sync(0xffffffffu, s,  o);
        s2 += __shfl_xor_sync(0xffffffffu, s2, o);
    }
    __shared__ float rs[4], rs2[4];
    if ((t & 31) == 0) { rs[t>>5] = s; rs2[t>>5] = s2; }
    __syncthreads();
    float S  = rs[0]+rs[1]+rs[2]+rs[3];
    float S2 = rs2[0]+rs2[1]+rs2[2]+rs2[3];
    float mu  = S * (1.0f/128.0f);
    float var = S2 * (1.0f/128.0f) - mu*mu;
    float rstd = rsqrtf(var + 1e-5f);
    g_xn[(long long)row*DM + t] = (v - mu) * rstd * g[t] + bb[t];
}

// ============================================================ Q/K projection (+ bf16 hi/lo epilogue)
__global__ void __launch_bounds__(256) proj_kernel(const float* __restrict__ W, int which) {
    __shared__ float At[32*68];
    __shared__ float Wt[32*68];
    int m0 = blockIdx.x * 64;
    int n0 = blockIdx.y * 64;
    int tid = threadIdx.x;
    int og = tid & 15, sg = tid >> 4;
    float acc[16];
    #pragma unroll
    for (int i = 0; i < 16; i++) acc[i] = 0.f;

    for (int kc = 0; kc < 128; kc += 32) {
        for (int i = tid; i < 2048; i += 256) {
            int k = i & 31, r = i >> 5;
            At[k*68 + r] = g_xn[(long long)(m0 + r)*128 + kc + k];
            Wt[k*68 + r] = W[(long long)(n0 + r)*128 + kc + k];
        }
        __syncthreads();
        #pragma unroll 8
        for (int k = 0; k < 32; k++) {
            float4 a = *(const float4*)&At[k*68 + sg*4];
            float4 w = *(const float4*)&Wt[k*68 + og*4];
            acc[ 0] += a.x*w.x; acc[ 1] += a.x*w.y; acc[ 2] += a.x*w.z; acc[ 3] += a.x*w.w;
            acc[ 4] += a.y*w.x; acc[ 5] += a.y*w.y; acc[ 6] += a.y*w.z; acc[ 7] += a.y*w.w;
            acc[ 8] += a.z*w.x; acc[ 9] += a.z*w.y; acc[10] += a.z*w.z; acc[11] += a.z*w.w;
            acc[12] += a.w*w.x; acc[13] += a.w*w.y; acc[14] += a.w*w.z; acc[15] += a.w*w.w;
        }
        __syncthreads();
    }
    __nv_bfloat16* hiA = which ? g_khi : g_qhi;
    __nv_bfloat16* loA = which ? g_klo : g_qlo;
    int col0 = n0 + og*4;
    int h  = col0 >> 7;
    int d0 = col0 & 127;
    #pragma unroll
    for (int i = 0; i < 4; i++) {
        int row = m0 + sg*4 + i;
        int b = row >> 10, s = row & 1023;
        int key = which ? ((s & 31)*32 + (s >> 5)) : s;   // spatial swap for K
        if (!which) {
            float4 st = make_float4(acc[i*4+0], acc[i*4+1], acc[i*4+2], acc[i*4+3]);
            *(float4*)&g_Q[(long long)(b*1024 + s)*1024 + col0] = st;
        }
        __nv_bfloat16 hh[4], ll[4];
        #pragma unroll
        for (int j = 0; j < 4; j++) cvt_hilo(acc[i*4+j], hh[j], ll[j]);
        long long base = ((long long)(b*8 + h)*1024 + key)*128 + d0;
        uint2 ph = make_uint2(pack2(hh[0], hh[1]), pack2(hh[2], hh[3]));
        uint2 pl = make_uint2(pack2(ll[0], ll[1]), pack2(ll[2], ll[3]));
        *(uint2*)&hiA[base] = ph;
        *(uint2*)&loA[base] = pl;
    }
}

// ============================================================ xn transpose -> bf16 hi/lo [b][d][key]
__global__ void __launch_bounds__(256) cvt_xt_kernel() {
    __shared__ __nv_bfloat16 t[128*136];
    int kc = blockIdx.x, b = blockIdx.y;
    int tid = threadIdx.x;
    for (int pass = 0; pass < 2; pass++) {
        for (int i = tid; i < 4096; i += 256) {      // 128 keys x 32 float4
            int key = i >> 5, ds = i & 31;
            float4 v = *(const float4*)&g_xn[(long long)(b*1024 + kc*128 + key)*128 + ds*4];
            float vv[4] = {v.x, v.y, v.z, v.w};
            #pragma unroll
            for (int j = 0; j < 4; j++) {
                __nv_bfloat16 hi = __float2bfloat16(vv[j]);
                __nv_bfloat16 o = pass ? __float2bfloat16(vv[j] - __bfloat162float(hi)) : hi;
                t[(ds*4 + j)*136 + key] = o;
            }
        }
        __syncthreads();
        __nv_bfloat16* dst = pass ? g_xtlo : g_xthi;
        for (int i = tid; i < 2048; i += 256) {      // 128 d x 16 uint4
            int d = i >> 4, seg = i & 15;
            *(uint4*)&dst[((long long)(b*128 + d))*1024 + kc*128 + seg*8] =
                *(const uint4*)&t[d*136 + seg*8];
        }
        __syncthreads();
    }
}

// ============================================================ relative-embedding scores
__global__ void __launch_bounds__(256) rel_kernel(const float* __restrict__ re_emb,
                                                  const float* __restrict__ ce_emb) {
    int bs = blockIdx.x;
    int s  = bs & 1023;
    int iq = s >> 5, jq = s & 31;
    __shared__ float qr[1024];
    __shared__ float re[32*68];
    __shared__ float ce[32*68];
    int tid = threadIdx.x;
    for (int i = tid; i < 256; i += 256)
        *(float4*)&qr[i*4] = *(const float4*)&g_Q[(long long)bs*1024 + i*4];
    for (int i = tid; i < 512; i += 256) {
        int v = i >> 4, d4 = i & 15;
        *(float4*)&re[v*68 + d4*4] = *(const float4*)&re_emb[(v - iq + 31)*64 + d4*4];
        *(float4*)&ce[v*68 + d4*4] = *(const float4*)&ce_emb[(v - jq + 31)*64 + d4*4];
    }
    __syncthreads();
    int h = tid >> 5, v = tid & 31;
    float a = 0.f, c = 0.f;
    #pragma unroll
    for (int dd = 0; dd < 16; dd++) {
        float4 qa = *(const float4*)&qr[h*128 + dd*4];
        float4 qb = *(const float4*)&qr[h*128 + 64 + dd*4];
        float4 rr = *(const float4*)&re[v*68 + dd*4];
        float4 cc = *(const float4*)&ce[v*68 + dd*4];
        a += qa.x*rr.x + qa.y*rr.y + qa.z*rr.z + qa.w*rr.w;
        c += qb.x*cc.x + qb.y*cc.y + qb.z*cc.z + qb.w*cc.w;
    }
    g_RS[((long long)bs*8 + h)*32 + v] = a;
    g_CS[((long long)bs*8 + h)*32 + v] = c;
}

// ============================================================ fused attention (mma.sync bf16 hi/lo)
// block = (iq, h, b), 256 threads = 8 warps.
#define SM_KH 131072
#define SM_KL 165888
#define SM_QH 200704
#define SM_QL 209408
#define SM_RS 218112
#define SM_CS 222208
#define ATTN_SMEM 226304
#define PB 272   // bf16 row pitch in bytes (136 elems)

__global__ void __launch_bounds__(256, 1) attn_mma_kernel(float* __restrict__ probs) {
    extern __shared__ char sm[];
    float* S   = (float*)sm;
    char*  KH  = sm + SM_KH;
    char*  KL  = sm + SM_KL;
    char*  QH  = sm + SM_QH;
    char*  QL  = sm + SM_QL;
    float* RSs = (float*)(sm + SM_RS);
    float* CSs = (float*)(sm + SM_CS);
    uint32_t uS  = smem_u32(sm);
    uint32_t uKH = uS + SM_KH, uKL = uS + SM_KL;
    uint32_t uQH = uS + SM_QH, uQL = uS + SM_QL;

    int iq = blockIdx.x, h = blockIdx.y, b = blockIdx.z;
    int tid = threadIdx.x;
    int w = tid >> 5, l = tid & 31;

    // ---- load Q hi/lo tiles (32 x 128) + RS/CS ----
    {
        long long qb = ((long long)(b*8 + h)*1024 + iq*32)*128;
        const uint4* sh = (const uint4*)&g_qhi[qb];
        const uint4* sl = (const uint4*)&g_qlo[qb];
        for (int i = tid; i < 512; i += 256) {
            int r = i >> 4, seg = i & 15;
            *(uint4*)(QH + r*PB + seg*16) = sh[i];
            *(uint4*)(QL + r*PB + seg*16) = sl[i];
        }
        for (int i = tid; i < 1024; i += 256) {
            int j = i >> 5, v = i & 31;
            long long rb = ((long long)(b*1024 + iq*32 + j)*8 + h)*32 + v;
            RSs[i] = g_RS[rb];
            CSs[i] = g_CS[rb];
        }
    }

    // lane-invariant fragment addresses
    uint32_t aRow  = (uint32_t)(l & 15);
    uint32_t aColB = (uint32_t)((l >> 4) * 16);
    uint32_t bRow  = (uint32_t)(l & 7);
    uint32_t bColB = (uint32_t)(((l >> 3) & 1) * 16);

    // -------- Phase 1: S = Q . K^T --------
    for (int kt = 0; kt < 8; kt++) {
        __syncthreads();
        {
            long long kb = ((long long)(b*8 + h)*1024 + kt*128)*128;
            const uint4* sh = (const uint4*)&g_khi[kb];
            const uint4* sl = (const uint4*)&g_klo[kb];
            for (int i = tid; i < 2048; i += 256) {
                int r = i >> 4, seg = i & 15;
                *(uint4*)(KH + r*PB + seg*16) = sh[i];
                *(uint4*)(KL + r*PB + seg*16) = sl[i];
            }
        }
        __syncthreads();
        float C[2][2][4];
        #pragma unroll
        for (int mt = 0; mt < 2; mt++)
            #pragma unroll
            for (int nt = 0; nt < 2; nt++)
                #pragma unroll
                for (int i = 0; i < 4; i++) C[mt][nt][i] = 0.f;
        #pragma unroll
        for (int k8 = 0; k8 < 8; k8++) {
            uint32_t kb = (uint32_t)(k8*32);
            uint32_t Ah[2][4], Al[2][4], Bh[2][2], Bl[2][2];
            ldm_x4(Ah[0], uQH + aRow*PB        + kb + aColB);
            ldm_x4(Ah[1], uQH + (aRow+16)*PB   + kb + aColB);
            ldm_x4(Al[0], uQL + aRow*PB        + kb + aColB);
            ldm_x4(Al[1], uQL + (aRow+16)*PB   + kb + aColB);
            uint32_t r0 = (uint32_t)(w*16) + bRow;
            ldm_x2(Bh[0], uKH + r0*PB       + kb + bColB);
            ldm_x2(Bh[1], uKH + (r0+8)*PB   + kb + bColB);
            ldm_x2(Bl[0], uKL + r0*PB       + kb + bColB);
            ldm_x2(Bl[1], uKL + (r0+8)*PB   + kb + bColB);
            #pragma unroll
            for (int mt = 0; mt < 2; mt++)
                #pragma unroll
                for (int nt = 0; nt < 2; nt++) {
                    mma16816(C[mt][nt], Ah[mt], Bh[nt]);
                    mma16816(C[mt][nt], Ah[mt], Bl[nt]);
                    mma16816(C[mt][nt], Al[mt], Bh[nt]);
                }
        }
        #pragma unroll
        for (int mt = 0; mt < 2; mt++)
            #pragma unroll
            for (int nt = 0; nt < 2; nt++) {
                int q   = mt*16 + (l >> 2);
                int key = kt*128 + w*16 + nt*8 + 2*(l & 3);
                *(float2*)&S[q*1024 + key]     = make_float2(C[mt][nt][0], C[mt][nt][1]);
                *(float2*)&S[(q+8)*1024 + key] = make_float2(C[mt][nt][2], C[mt][nt][3]);
            }
    }
    __syncthreads();

    // -------- Phase 2: bias + scale + softmax (+ probs) --------
    {
        for (int rr = 0; rr < 4; rr++) {
            int q = w*4 + rr;
            float* Srow = S + q*1024;
            float mx = -1e30f;
            for (int j = l; j < 1024; j += 32) {
                float val = (Srow[j] + RSs[q*32 + (j & 31)] + CSs[q*32 + (j >> 5)]) * INV_SQRT_D;
                Srow[j] = val;
                mx = fmaxf(mx, val);
            }
            #pragma unroll
            for (int o = 16; o; o >>= 1) mx = fmaxf(mx, __shfl_xor_sync(0xffffffffu, mx, o));
            float sum = 0.f;
            for (int j = l; j < 1024; j += 32) {
                float e = __expf(Srow[j] - mx);
                Srow[j] = e;
                sum += e;
            }
            #pragma unroll
            for (int o = 16; o; o >>= 1) sum += __shfl_xor_sync(0xffffffffu, sum, o);
            float is = 1.0f / sum;
            if (probs) {
                long long pbs = ((((long long)b*32 + q)*32 + iq)*8 + h)*1024;
                for (int j = l; j < 1024; j += 32) {
                    float p = Srow[j] * is;
                    Srow[j] = p;
                    probs[pbs + j] = p;
                }
            } else {
                for (int j = l; j < 1024; j += 32) Srow[j] *= is;
            }
        }
    }

    // -------- Phase 3: C = P . X  (accumulate over 8 key tiles) --------
    float C2[2][2][4];
    #pragma unroll
    for (int mt = 0; mt < 2; mt++)
        #pragma unroll
        for (int nt = 0; nt < 2; nt++)
            #pragma unroll
            for (int i = 0; i < 4; i++) C2[mt][nt][i] = 0.f;

    for (int kt = 0; kt < 8; kt++) {
        __syncthreads();
        // convert P tile (S fp32 -> QH/QL bf16 hi/lo)
        {
            int q = tid >> 3, s16 = (tid & 7)*16;
            const float* Sr = S + q*1024 + kt*128 + s16;
            __nv_bfloat16* dh = (__nv_bfloat16*)(QH + q*PB) + s16;
            __nv_bfloat16* dl = (__nv_bfloat16*)(QL + q*PB) + s16;
            #pragma unroll
            for (int j = 0; j < 16; j++) {
                float f = Sr[j];
                __nv_bfloat16 hi, lo; cvt_hilo(f, hi, lo);
                dh[j] = hi; dl[j] = lo;
            }
        }
        // load XT tile [d][key-local]
        {
            for (int i = tid; i < 2048; i += 256) {
                int d = i >> 4, seg = i & 15;
                long long src = ((long long)(b*128 + d))*1024 + kt*128 + seg*8;
                *(uint4*)(KH + d*PB + seg*16) = *(const uint4*)&g_xthi[src];
                *(uint4*)(KL + d*PB + seg*16) = *(const uint4*)&g_xtlo[src];
            }
        }
        __syncthreads();
        #pragma unroll
        for (int k8 = 0; k8 < 8; k8++) {
            uint32_t kb = (uint32_t)(k8*32);
            uint32_t Ah[2][4], Al[2][4], Bh[2][2], Bl[2][2];
            ldm_x4(Ah[0], uQH + aRow*PB        + kb + aColB);
            ldm_x4(Ah[1], uQH + (aRow+16)*PB   + kb + aColB);
            ldm_x4(Al[0], uQL + aRow*PB        + kb + aColB);
            ldm_x4(Al[1], uQL + (aRow+16)*PB   + kb + aColB);
            uint32_t r0 = (uint32_t)(w*16) + bRow;
            ldm_x2(Bh[0], uKH + r0*PB       + kb + bColB);
            ldm_x2(Bh[1], uKH + (r0+8)*PB   + kb + bColB);
            ldm_x2(Bl[0], uKL + r0*PB       + kb + bColB);
            ldm_x2(Bl[1], uKL + (r0+8)*PB   + kb + bColB);
            #pragma unroll
            for (int mt = 0; mt < 2; mt++)
                #pragma unroll
                for (int nt = 0; nt < 2; nt++) {
                    mma16816(C2[mt][nt], Ah[mt], Bh[nt]);
                    mma16816(C2[mt][nt], Ah[mt], Bl[nt]);
                    mma16816(C2[mt][nt], Al[mt], Bh[nt]);
                }
        }
    }
    // store context: spatial row = q*32 + iq
    #pragma unroll
    for (int mt = 0; mt < 2; mt++)
        #pragma unroll
        for (int nt = 0; nt < 2; nt++) {
            int q = mt*16 + (l >> 2);
            int d = w*16 + nt*8 + 2*(l & 3);
            *(float2*)&g_C[(long long)(b*1024 + q*32 + iq)*1024 + h*128 + d] =
                make_float2(C2[mt][nt][0], C2[mt][nt][1]);
            *(float2*)&g_C[(long long)(b*1024 + (q+8)*32 + iq)*1024 + h*128 + d] =
                make_float2(C2[mt][nt][2], C2[mt][nt][3]);
        }
}

// ============================================================ output projection + residual
__global__ void __launch_bounds__(512) out_kernel(const float* __restrict__ Wv,
                                                  const float* __restrict__ bv,
                                                  float* __restrict__ out) {
    __shared__ float At[32*68];
    __shared__ float Wt[32*132];
    int m0 = blockIdx.x * 64;
    int tid = threadIdx.x;
    int og = tid & 31, sg = tid >> 5;
    float acc[16];
    #pragma unroll
    for (int i = 0; i < 16; i++) acc[i] = 0.f;

    for (int kc = 0; kc < 1024; kc += 32) {
        for (int i = tid; i < 2048; i += 512) {
            int k = i & 31, r = i >> 5;
            At[k*68 + r] = g_C[(long long)(m0 + r)*1024 + kc + k];
        }
        for (int i = tid; i < 4096; i += 512) {
            int k = i & 31, o = i >> 5;
            Wt[k*132 + o] = Wv[(long long)o*1024 + kc + k];
        }
        __syncthreads();
        #pragma unroll 8
        for (int k = 0; k < 32; k++) {
            float4 a = *(const float4*)&At[k*68 + sg*4];
            float4 w = *(const float4*)&Wt[k*132 + og*4];
            acc[ 0] += a.x*w.x; acc[ 1] += a.x*w.y; acc[ 2] += a.x*w.z; acc[ 3] += a.x*w.w;
            acc[ 4] += a.y*w.x; acc[ 5] += a.y*w.y; acc[ 6] += a.y*w.z; acc[ 7] += a.y*w.w;
            acc[ 8] += a.z*w.x; acc[ 9] += a.z*w.y; acc[10] += a.z*w.z; acc[11] += a.z*w.w;
            acc[12] += a.w*w.x; acc[13] += a.w*w.y; acc[14] += a.w*w.z; acc[15] += a.w*w.w;
        }
        __syncthreads();
    }
    if (out) {
        float4 b4 = *(const float4*)&bv[og*4];
        #pragma unroll
        for (int i = 0; i < 4; i++) {
            int row = m0 + sg*4 + i;
            float4 x4 = *(const float4*)&g_xn[(long long)row*128 + og*4];
            float4 r4;
            r4.x = acc[i*4+0] + b4.x + x4.x;
            r4.y = acc[i*4+1] + b4.y + x4.y;
            r4.z = acc[i*4+2] + b4.z + x4.z;
            r4.w = acc[i*4+3] + b4.w + x4.w;
            *(float4*)&out[(long long)row*128 + og*4] = r4;
        }
    }
}

// ============================================================ launch
extern "C" void kernel_launch(void* const* d_in, const int* in_sizes, int n_in,
                              void* d_out, int out_size) {
    const float* x   = (const float*)d_in[0];
    const float* rem = (const float*)d_in[1];
    const float* cem = (const float*)d_in[2];
    const float* Wq  = (const float*)d_in[3];
    const float* Wk  = (const float*)d_in[4];
    const float* Wv  = (const float*)d_in[5];
    const float* bv  = (const float*)d_in[6];
    const float* lg  = (const float*)d_in[7];
    const float* lb  = (const float*)d_in[8];

    const long long ON = 1048576LL;
    const long long PN = 67108864LL;
    float* outp  = (float*)d_out;
    float* probs = nullptr;
    if ((long long)out_size >= ON + PN) {
        probs = (float*)d_out + ON;
    } else if ((long long)out_size == PN) {
        probs = (float*)d_out;
        outp  = nullptr;
    }

    static int smem_ok = -1;
    if (smem_ok < 0) {
        cudaError_t e = cudaFuncSetAttribute(
            attn_mma_kernel, cudaFuncAttributeMaxDynamicSharedMemorySize, ATTN_SMEM);
        smem_ok = (e == cudaSuccess) ? 1 : 0;
        if (!smem_ok) cudaGetLastError();
    }

    ln_kernel<<<8192, 128>>>(x, lg, lb);
    proj_kernel<<<dim3(128, 16), 256>>>(Wq, 0);
    proj_kernel<<<dim3(128, 16), 256>>>(Wk, 1);
    cvt_xt_kernel<<<dim3(8, 8), 256>>>();
    rel_kernel<<<8192, 256>>>(rem, cem);
    attn_mma_kernel<<<dim3(32, NH, NB), 256, ATTN_SMEM>>>(probs);
    out_kernel<<<128, 512>>>(Wv, bv, outp);
}